// round 1
// baseline (speedup 1.0000x reference)
#include <cuda_runtime.h>

// Problem constants (fixed by setup_inputs)
#define HH_IMG 512
#define WW_IMG 512
#define TILE_W 32
#define TILE_H 8
#define HALO_W 34
#define HALO_H 10
#define PLANE  (HALO_W * HALO_H)   // 340
#define NPLANES 30                 // 3 (Z) + 27 (w_pre)

// Fused HMM estimator update:
//  phase 1: per halo pixel compute Z[3] and w_pre[27] into shared planes
//  phase 2: per output pixel: 10 grouped 3x3 convs (Z + 9 tangents),
//           softmax -> u_kp1, softmax-JVP -> w_kp1
__global__ __launch_bounds__(256)
void hmm_update_kernel(const float* __restrict__ obs,
                       const float* __restrict__ Pm,
                       const float* __restrict__ u_k,
                       const float* __restrict__ w_k,
                       const float* __restrict__ conv_w,
                       const float* __restrict__ conv_b,
                       float* __restrict__ out)
{
    __shared__ float sm[NPLANES * PLANE];   // planar: plane c at sm[c*PLANE + idx]
    __shared__ float smW[81];
    __shared__ float smB[3];

    const int tid = threadIdx.x;
    if (tid < 81) smW[tid] = conv_w[tid];
    if (tid < 3)  smB[tid] = conv_b[tid];

    const int base_w = blockIdx.x * TILE_W;
    const int base_h = blockIdx.y * TILE_H;

    // P is tiny; read via read-only cache (broadcast) in phase 1.
    const float p00 = __ldg(&Pm[0]), p01 = __ldg(&Pm[1]), p02 = __ldg(&Pm[2]);
    const float p10 = __ldg(&Pm[3]), p11 = __ldg(&Pm[4]), p12 = __ldg(&Pm[5]);
    const float p20 = __ldg(&Pm[6]), p21 = __ldg(&Pm[7]), p22 = __ldg(&Pm[8]);

    // ---------------- Phase 1: fill halo planes ----------------
    for (int k = tid; k < PLANE; k += 256) {
        const int lx = k % HALO_W;
        const int ly = k / HALO_W;
        const int gw = base_w + lx - 1;
        const int gh = base_h + ly - 1;

        float Z[3];
        float wp[27];

        if ((unsigned)gw < (unsigned)WW_IMG && (unsigned)gh < (unsigned)HH_IMG) {
            const int pix = gh * WW_IMG + gw;
            const float o0 = __ldg(&obs[pix * 3 + 0]);
            const float o1 = __ldg(&obs[pix * 3 + 1]);
            const float o2 = __ldg(&obs[pix * 3 + 2]);
            const float u0 = __ldg(&u_k[pix * 3 + 0]);
            const float u1 = __ldg(&u_k[pix * 3 + 1]);
            const float u2 = __ldg(&u_k[pix * 3 + 2]);

            // b[s] = sum_o P[o,s] * obs[o]
            const float b0 = p00 * o0 + p10 * o1 + p20 * o2;
            const float b1 = p01 * o0 + p11 * o1 + p21 * o2;
            const float b2 = p02 * o0 + p12 * o1 + p22 * o2;

            const float Bu0 = b0 * u0, Bu1 = b1 * u1, Bu2 = b2 * u2;
            const float bu = Bu0 + Bu1 + Bu2;
            const float inv = __frcp_rn(bu);
            const float inv2 = inv * inv;
            Z[0] = Bu0 * inv; Z[1] = Bu1 * inv; Z[2] = Bu2 * inv;

            const float ovec[3] = {o0, o1, o2};
            const float uvec[3] = {u0, u1, u2};
            const float bvec[3] = {b0, b1, b2};
            const float Buv[3]  = {Bu0, Bu1, Bu2};

            const float* wkp = w_k + (long)pix * 27;

            float du[27];
            float sdu[9];
            #pragma unroll
            for (int t = 0; t < 9; t++) sdu[t] = 0.f;

            // du[s,i,j] = obs[i]*u[s]*(s==j) + b[s]*w_k[s,i,j]
            #pragma unroll
            for (int s = 0; s < 3; s++) {
                #pragma unroll
                for (int i = 0; i < 3; i++) {
                    #pragma unroll
                    for (int j = 0; j < 3; j++) {
                        float d = bvec[s] * wkp[s * 9 + i * 3 + j];
                        if (j == s) d += ovec[i] * uvec[s];
                        du[s * 9 + i * 3 + j] = d;
                        sdu[i * 3 + j] += d;
                    }
                }
            }
            // w_pre[s,i,j] = du*inv - sdu*Bu[s]*inv^2
            #pragma unroll
            for (int s = 0; s < 3; s++) {
                const float c = Buv[s] * inv2;
                #pragma unroll
                for (int t = 0; t < 9; t++) {
                    wp[s * 9 + t] = du[s * 9 + t] * inv - sdu[t] * c;
                }
            }
        } else {
            #pragma unroll
            for (int s = 0; s < 3; s++) Z[s] = 0.f;
            #pragma unroll
            for (int t = 0; t < 27; t++) wp[t] = 0.f;
        }

        // Plane layout: g=0 -> Z channels (plane s), g=1+t' (t'=i*3+j) -> plane 3+t'*3+s
        #pragma unroll
        for (int s = 0; s < 3; s++) sm[s * PLANE + k] = Z[s];
        #pragma unroll
        for (int s = 0; s < 3; s++) {
            #pragma unroll
            for (int t = 0; t < 9; t++) {
                sm[(3 + t * 3 + s) * PLANE + k] = wp[s * 9 + t];
            }
        }
    }
    __syncthreads();

    // ---------------- Phase 2: grouped conv + softmax + JVP ----------------
    const int lx = tid & 31;
    const int ly = tid >> 5;
    const int hx = lx + 1;
    const int hy = ly + 1;

    float acc[10][3];
    #pragma unroll
    for (int g = 0; g < 10; g++) {
        acc[g][0] = 0.f; acc[g][1] = 0.f; acc[g][2] = 0.f;
    }

    #pragma unroll
    for (int t = 0; t < 9; t++) {
        const int kh = t / 3, kw = t % 3;
        const int nb = (hy + kh - 1) * HALO_W + (hx + kw - 1);
        #pragma unroll
        for (int si = 0; si < 3; si++) {
            // conv_w[o][si][kh][kw] = smW[(o*3+si)*9 + t]
            const float w0 = smW[(0 + si) * 9 + t];
            const float w1 = smW[(3 + si) * 9 + t];
            const float w2 = smW[(6 + si) * 9 + t];
            #pragma unroll
            for (int g = 0; g < 10; g++) {
                const float v = sm[(g * 3 + si) * PLANE + nb];
                acc[g][0] = fmaf(w0, v, acc[g][0]);
                acc[g][1] = fmaf(w1, v, acc[g][1]);
                acc[g][2] = fmaf(w2, v, acc[g][2]);
            }
        }
    }

    const int gw = base_w + lx;
    const int gh = base_h + ly;
    const int pix = gh * WW_IMG + gw;

    // softmax over y = conv(Z) + bias
    const float y0 = acc[0][0] + smB[0];
    const float y1 = acc[0][1] + smB[1];
    const float y2 = acc[0][2] + smB[2];
    const float m = fmaxf(y0, fmaxf(y1, y2));
    const float e0 = __expf(y0 - m);
    const float e1 = __expf(y1 - m);
    const float e2 = __expf(y2 - m);
    const float rs = __frcp_rn(e0 + e1 + e2);
    const float q0 = e0 * rs, q1 = e1 * rs, q2 = e2 * rs;

    out[pix * 3 + 0] = q0;
    out[pix * 3 + 1] = q1;
    out[pix * 3 + 2] = q2;

    float* ow = out + (long)HH_IMG * WW_IMG * 3 + (long)pix * 27;
    #pragma unroll
    for (int t = 0; t < 9; t++) {
        const float d0 = acc[1 + t][0];
        const float d1 = acc[1 + t][1];
        const float d2 = acc[1 + t][2];
        const float dot = q0 * d0 + q1 * d1 + q2 * d2;
        ow[0 * 9 + t] = q0 * (d0 - dot);
        ow[1 * 9 + t] = q1 * (d1 - dot);
        ow[2 * 9 + t] = q2 * (d2 - dot);
    }
}

extern "C" void kernel_launch(void* const* d_in, const int* in_sizes, int n_in,
                              void* d_out, int out_size)
{
    const float* obs    = (const float*)d_in[0];
    const float* Pm     = (const float*)d_in[1];
    const float* u_k    = (const float*)d_in[2];
    const float* w_k    = (const float*)d_in[3];
    const float* conv_w = (const float*)d_in[4];
    const float* conv_b = (const float*)d_in[5];
    float* out = (float*)d_out;

    dim3 grid(WW_IMG / TILE_W, HH_IMG / TILE_H);
    dim3 block(256);
    hmm_update_kernel<<<grid, block>>>(obs, Pm, u_k, w_k, conv_w, conv_b, out);
}